// round 14
// baseline (speedup 1.0000x reference)
#include <cuda_runtime.h>
#include <cuda_fp16.h>
#include <stdint.h>
#include <math.h>

#define B_SZ 8192
#define F    40
#define E    8
#define FE   320
#define RDIM 5
#define P    780
#define K1   12480
#define N1   1024
#define N2   512

// ---- GEMM tiling ----
#define BM 128
#define BN 128
#define BK 32
#define TILE_B 8192                      // one matrix tile: 128 rows x 64B swizzled
#define KT_B   16384                     // one kt sub-stage: A + B
#define PAIR_B 32768                     // pair stage: 2 kt
#define NPAIRS 3
#define GEMM_SMEM (NPAIRS * PAIR_B)      // 98304 -> 2 CTAs/SM

// ---- stream-K for GEMM1 ----
#define NKT1  (K1 / BK)                  // 390 kt per tile
#define NTM1  (B_SZ / BM)                // 64
#define NTN1  (N1 / BN)                  // 8
#define NT1   (NTM1 * NTN1)              // 512 tiles
#define NCTA1 296                        // 148 SMs x 2 CTAs
#define U1    ((size_t)NT1 * NKT1)       // 199680 work units

// -------------------- device scratch --------------------
__device__ __half g_h [(size_t)B_SZ * K1];
__device__ __half g_w1[(size_t)N1 * K1];
__device__ __half g_y1[(size_t)B_SZ * N1];
__device__ __half g_w2[(size_t)N2 * N1];
__device__ float  g_y2[(size_t)B_SZ * N2];
__device__ float  g_p0[(size_t)NT1 * BM * BN];   // stream-K partial (k-head)
__device__ float  g_p1[(size_t)NT1 * BM * BN];   // stream-K partial (k-tail)

// -------------------- helpers --------------------
__device__ __forceinline__ uint32_t smem_u32(const void* p) {
    uint32_t a;
    asm("{ .reg .u64 t; cvta.to.shared.u64 t, %1; cvt.u32.u64 %0, t; }" : "=r"(a) : "l"(p));
    return a;
}
__device__ __forceinline__ void cp16(uint32_t dst, const void* src) {
    asm volatile("cp.async.cg.shared.global [%0], [%1], 16;" :: "r"(dst), "l"(src));
}
__device__ __forceinline__ void ldsm_x4(uint32_t* r, uint32_t addr) {
    asm volatile("ldmatrix.sync.aligned.m8n8.x4.shared.b16 {%0,%1,%2,%3}, [%4];"
                 : "=r"(r[0]), "=r"(r[1]), "=r"(r[2]), "=r"(r[3]) : "r"(addr));
}
__device__ __forceinline__ void mma_fp16(float* c, const uint32_t* a, const uint32_t* b) {
    asm volatile(
        "mma.sync.aligned.m16n8k16.row.col.f32.f16.f16.f32 "
        "{%0,%1,%2,%3}, {%4,%5,%6,%7}, {%8,%9}, {%0,%1,%2,%3};"
        : "+f"(c[0]), "+f"(c[1]), "+f"(c[2]), "+f"(c[3])
        : "r"(a[0]), "r"(a[1]), "r"(a[2]), "r"(a[3]), "r"(b[0]), "r"(b[1]));
}
// swizzled byte offset within an 8KB tile: row r (0..127), byte col bc (0..63, 16B-aligned)
__device__ __forceinline__ uint32_t swz(int r, int bc) {
    return (uint32_t)(r * 64 + ((((bc) >> 4) ^ ((r >> 1) & 3)) << 4));
}
__device__ __forceinline__ uint32_t pack2h(float a, float b) {
    __half2 h = __floats2half2_rn(a, b);
    return *(uint32_t*)&h;
}

// ---------------------------------------------------------------------------
// Kernel A: BN + SENet + bilinear -> h (fp16), vectorized 16B stores.
// ---------------------------------------------------------------------------
__global__ __launch_bounds__(256) void feat_kernel(
    const float* __restrict__ emb,  const float* __restrict__ bn_w,
    const float* __restrict__ bn_b, const float* __restrict__ bn_m,
    const float* __restrict__ bn_v, const float* __restrict__ se_w1,
    const float* __restrict__ se_w2,const float* __restrict__ w_bl,
    __half* __restrict__ h_out)
{
    __shared__ float sV[FE], sT[FE], sZ[F], sH[RDIM], sA[F], sW[E*E];
    __shared__ unsigned char s_pi[P], s_pj[P];

    const int tid = threadIdx.x;
    const int b   = blockIdx.x;

    if (tid == 0) {
        int p = 0;
        for (int i = 0; i < F; i++)
            for (int j = i + 1; j < F; j++) { s_pi[p] = (unsigned char)i; s_pj[p] = (unsigned char)j; p++; }
    }
    if (tid < E*E) sW[tid] = w_bl[tid];

    for (int idx = tid; idx < FE; idx += 256) {
        float x   = emb[(size_t)b * FE + idx];
        float inv = rsqrtf(bn_v[idx] + 1e-5f);
        sV[idx]   = (x - bn_m[idx]) * inv * bn_w[idx] + bn_b[idx];
    }
    __syncthreads();

    if (tid < F) {
        float s = 0.f;
        #pragma unroll
        for (int e = 0; e < E; e++) s += sV[tid * E + e];
        sZ[tid] = s * (1.f / E);
    }
    __syncthreads();

    if (tid < RDIM) {
        float s = 0.f;
        #pragma unroll
        for (int f = 0; f < F; f++) s += sZ[f] * se_w1[tid * F + f];
        sH[tid] = fmaxf(s, 0.f);
    }
    __syncthreads();

    if (tid < F) {
        float s = 0.f;
        #pragma unroll
        for (int r = 0; r < RDIM; r++) s += sH[r] * se_w2[tid * RDIM + r];
        sA[tid] = fmaxf(s, 0.f);
    }

    for (int idx = tid; idx < FE; idx += 256) {
        int f = idx >> 3, d = idx & 7;
        float s = 0.f;
        #pragma unroll
        for (int e = 0; e < E; e++) s += sV[f * E + e] * sW[d * E + e];
        sT[idx] = s;
    }
    __syncthreads();

    __half* oh = h_out + (size_t)b * K1;
    for (int g = tid; g < 2 * P; g += 256) {
        const int p = (g < P) ? g : (g - P);
        const int i = s_pi[p], j = s_pj[p];
        const float sc = (g < P) ? (sA[i] * sA[j]) : 1.f;
        const float4 ta = *(const float4*)&sT[i * E];
        const float4 tb = *(const float4*)&sT[i * E + 4];
        const float4 va = *(const float4*)&sV[j * E];
        const float4 vb = *(const float4*)&sV[j * E + 4];
        uint4 hv;
        hv.x = pack2h((ta.x * va.x) * sc, (ta.y * va.y) * sc);
        hv.y = pack2h((ta.z * va.z) * sc, (ta.w * va.w) * sc);
        hv.z = pack2h((tb.x * vb.x) * sc, (tb.y * vb.y) * sc);
        hv.w = pack2h((tb.z * vb.z) * sc, (tb.w * vb.w) * sc);
        *(uint4*)(oh + (size_t)g * 8) = hv;
    }
}

// ---------------------------------------------------------------------------
// Weight convert fp32 -> fp16, vectorized (n4 = n/4)
// ---------------------------------------------------------------------------
__global__ __launch_bounds__(256) void split_kernel(
    const float* __restrict__ src, __half* __restrict__ dst, size_t n4)
{
    for (size_t i = (size_t)blockIdx.x * blockDim.x + threadIdx.x; i < n4;
         i += (size_t)gridDim.x * blockDim.x) {
        float4 v = ((const float4*)src)[i];
        uint2 hv;
        hv.x = pack2h(v.x, v.y);
        hv.y = pack2h(v.z, v.w);
        *(uint2*)(dst + i * 4) = hv;
    }
}

// ---------------------------------------------------------------------------
// GEMM1 stream-K phase 1 (fp16): 296 persistent CTAs.
// Pair-stage pipeline: 2 kt per wait+barrier, 3 pair-stages in flight.
// ---------------------------------------------------------------------------
__global__ void __launch_bounds__(256, 2) gemm1_sk(
    const __half* __restrict__ A, const __half* __restrict__ B,
    const float* __restrict__ bias,
    __half* __restrict__ Oh,
    float* __restrict__ p0, float* __restrict__ p1)
{
    extern __shared__ char smem[];
    const uint32_t sb  = smem_u32(smem);
    const int tid  = threadIdx.x;
    const int warp = tid >> 5, lane = tid & 31;
    const int wm   = warp & 3;
    const int wn   = warp >> 2;

    // per-thread load coords (2 x 16B chunks per matrix per kt)
    const int r0 = tid >> 2, c0 = tid & 3;
    const uint32_t s_off0 = swz(r0, c0 * 16);
    const uint32_t s_off1 = swz(r0 + 64, c0 * 16);
    const size_t rowK  = (size_t)K1 * 2;
    const size_t g_off0 = (size_t)r0 * rowK + c0 * 16;
    const size_t g_off1 = (size_t)(r0 + 64) * rowK + c0 * 16;

    // ldmatrix lane coords (tile-local)
    const int a_row = wm * 32 + (lane & 15);
    const int a_col = (lane >> 4) * 8;
    const int b_row = wn * 64 + ((lane >> 4) << 3) + (lane & 7);
    const int b_col = ((lane >> 3) & 1) * 8;

    size_t beg = (size_t)blockIdx.x       * U1 / NCTA1;
    size_t end = (size_t)(blockIdx.x + 1) * U1 / NCTA1;

    bool first_seg = true;
    while (beg < end) {
        const int t  = (int)(beg / NKT1);
        const int k0 = (int)(beg % NKT1);
        int L = NKT1 - k0;
        if ((size_t)L > end - beg) L = (int)(end - beg);
        const int bm = t >> 3, bn = t & 7;
        const int NP = (L + 1) >> 1;           // pairs in this segment

        const char* pA = (const char*)(A + (size_t)bm * BM * K1);
        const char* pB = (const char*)(B + (size_t)bn * BN * K1);

        float acc[2][8][4];
        #pragma unroll
        for (int i = 0; i < 2; i++)
            #pragma unroll
            for (int j = 0; j < 8; j++)
                #pragma unroll
                for (int r = 0; r < 4; r++) acc[i][j][r] = 0.f;

        auto load_kt = [&](uint32_t base, int kt) {
            const size_t koff = (size_t)kt * (BK * 2);
            cp16(base + s_off0,          pA + g_off0 + koff);
            cp16(base + s_off1,          pA + g_off1 + koff);
            cp16(base + TILE_B + s_off0, pB + g_off0 + koff);
            cp16(base + TILE_B + s_off1, pB + g_off1 + koff);
        };
        auto load_pair = [&](int s, int pi) {
            const uint32_t base = sb + s * PAIR_B;
            const int kt = k0 + 2 * pi;
            load_kt(base, kt);
            if (2 * pi + 1 < L) load_kt(base + KT_B, kt + 1);
        };

        // barrier between segments: last ldsm of prev segment vs new writes
        if (!first_seg) __syncthreads();
        first_seg = false;

        load_pair(0, 0);
        asm volatile("cp.async.commit_group;" ::: "memory");
        if (NP > 1) load_pair(1, 1);
        asm volatile("cp.async.commit_group;" ::: "memory");

        for (int i = 0; i < NP; i++) {
            const int s = i % NPAIRS;
            asm volatile("cp.async.wait_group 1;" ::: "memory");
            __syncthreads();

            if (i + 2 < NP) load_pair((i + 2) % NPAIRS, i + 2);
            asm volatile("cp.async.commit_group;" ::: "memory");

            const int cnt = (2 * i + 2 <= L) ? 2 : 1;
            for (int sub = 0; sub < cnt; sub++) {
                const uint32_t baseA = sb + s * PAIR_B + sub * KT_B;
                const uint32_t baseB = baseA + TILE_B;
                #pragma unroll
                for (int ks = 0; ks < 2; ks++) {
                    const int k16 = ks * 16;
                    uint32_t af[2][4];
                    #pragma unroll
                    for (int mt = 0; mt < 2; mt++)
                        ldsm_x4(af[mt], baseA + swz(a_row + mt * 16, (k16 + a_col) * 2));
                    uint32_t bf[8][2];
                    #pragma unroll
                    for (int np = 0; np < 4; np++) {
                        uint32_t r[4];
                        ldsm_x4(r, baseB + swz(b_row + np * 16, (k16 + b_col) * 2));
                        bf[np*2][0]   = r[0]; bf[np*2][1]   = r[1];
                        bf[np*2+1][0] = r[2]; bf[np*2+1][1] = r[3];
                    }
                    #pragma unroll
                    for (int mt = 0; mt < 2; mt++)
                        #pragma unroll
                        for (int nt = 0; nt < 8; nt++)
                            mma_fp16(acc[mt][nt], af[mt], bf[nt]);
                }
            }
        }
        asm volatile("cp.async.wait_group 0;" ::: "memory");

        // ---- epilogue for this segment ----
        const bool full = (k0 == 0) && (L == NKT1);
        const int ml0 = wm * 32 + (lane >> 2);
        const int nl0 = wn * 64 + (lane & 3) * 2;
        if (full) {
            #pragma unroll
            for (int mt = 0; mt < 2; mt++)
                #pragma unroll
                for (int half = 0; half < 2; half++) {
                    const int m = bm * BM + ml0 + mt * 16 + half * 8;
                    #pragma unroll
                    for (int nt = 0; nt < 8; nt++) {
                        const int n = bn * BN + nl0 + nt * 8;
                        float v0 = fmaxf(acc[mt][nt][half*2+0] + __ldg(&bias[n]),   0.f);
                        float v1 = fmaxf(acc[mt][nt][half*2+1] + __ldg(&bias[n+1]), 0.f);
                        *(uint32_t*)(Oh + (size_t)m * N1 + n) = pack2h(v0, v1);
                    }
                }
        } else {
            float* pp = ((k0 == 0) ? p0 : p1) + (size_t)t * (BM * BN);
            #pragma unroll
            for (int mt = 0; mt < 2; mt++)
                #pragma unroll
                for (int half = 0; half < 2; half++) {
                    const int ml = ml0 + mt * 16 + half * 8;
                    #pragma unroll
                    for (int nt = 0; nt < 8; nt++) {
                        const int nl = nl0 + nt * 8;
                        float2 fv;
                        fv.x = acc[mt][nt][half*2+0];
                        fv.y = acc[mt][nt][half*2+1];
                        *(float2*)(pp + ml * BN + nl) = fv;
                    }
                }
        }
        beg += L;
    }
}

// ---------------------------------------------------------------------------
// GEMM1 stream-K phase 2: combine partials for split tiles (deterministic).
// ---------------------------------------------------------------------------
__global__ __launch_bounds__(256) void gemm1_fix(
    const float* __restrict__ p0, const float* __restrict__ p1,
    const float* __restrict__ bias,
    __half* __restrict__ Oh)
{
    const int t = blockIdx.x;
    const unsigned long long lo = (unsigned long long)t * NKT1;
    unsigned long long c = ((lo + 1) * NCTA1 + U1 - 1) / U1;
    if (c < 1 || c > NCTA1 - 1) return;
    unsigned long long bnd = c * U1 / NCTA1;
    if (bnd >= lo + NKT1) return;   // no interior boundary -> tile was whole

    const int bm = t >> 3, bn = t & 7;
    const float* a = p0 + (size_t)t * (BM * BN);
    const float* b = p1 + (size_t)t * (BM * BN);

    #pragma unroll 4
    for (int j = 0; j < (BM * BN) / 256; j++) {
        const int idx = threadIdx.x + j * 256;
        const int ml = idx >> 7, nl = idx & 127;
        const int n = bn * BN + nl;
        float v = fmaxf(a[idx] + b[idx] + bias[n], 0.f);
        Oh[(size_t)(bm * BM + ml) * N1 + n] = __float2half_rn(v);
    }
}

// ---------------------------------------------------------------------------
// GEMM2 (fp16, NT), classic tiled, pair-stage pipeline, writes fp32.
// K must be a multiple of 64 (K=1024 here).
// ---------------------------------------------------------------------------
__global__ void __launch_bounds__(256, 2) gemm_fp16(
    const __half* __restrict__ A, const __half* __restrict__ B,
    const float* __restrict__ bias,
    float* __restrict__ Of,
    int Nfull, int K)
{
    extern __shared__ char smem[];
    const uint32_t sb  = smem_u32(smem);
    const int tid  = threadIdx.x;
    const int warp = tid >> 5, lane = tid & 31;
    const int wm   = warp & 3;
    const int wn   = warp >> 2;
    const int bn   = blockIdx.x, bm = blockIdx.y;
    const int NP   = K / (2 * BK);   // pairs

    const char* pA = (const char*)(A + (size_t)bm * BM * K);
    const char* pB = (const char*)(B + (size_t)bn * BN * K);
    const size_t rowK = (size_t)K * 2;

    const int r0 = tid >> 2, c0 = tid & 3;
    const uint32_t s_off0 = swz(r0, c0 * 16);
    const uint32_t s_off1 = swz(r0 + 64, c0 * 16);
    const size_t  g_off0 = (size_t)r0 * rowK + c0 * 16;
    const size_t  g_off1 = (size_t)(r0 + 64) * rowK + c0 * 16;

    auto load_kt = [&](uint32_t base, int kt) {
        const size_t koff = (size_t)kt * (BK * 2);
        cp16(base + s_off0,          pA + g_off0 + koff);
        cp16(base + s_off1,          pA + g_off1 + koff);
        cp16(base + TILE_B + s_off0, pB + g_off0 + koff);
        cp16(base + TILE_B + s_off1, pB + g_off1 + koff);
    };
    auto load_pair = [&](int s, int pi) {
        const uint32_t base = sb + s * PAIR_B;
        load_kt(base, 2 * pi);
        load_kt(base + KT_B, 2 * pi + 1);
    };

    float acc[2][8][4];
    #pragma unroll
    for (int i = 0; i < 2; i++)
        #pragma unroll
        for (int j = 0; j < 8; j++)
            #pragma unroll
            for (int r = 0; r < 4; r++) acc[i][j][r] = 0.f;

    load_pair(0, 0);
    asm volatile("cp.async.commit_group;" ::: "memory");
    if (NP > 1) load_pair(1, 1);
    asm volatile("cp.async.commit_group;" ::: "memory");

    const int a_row = wm * 32 + (lane & 15);
    const int a_col = (lane >> 4) * 8;
    const int b_row = wn * 64 + ((lane >> 4) << 3) + (lane & 7);
    const int b_col = ((lane >> 3) & 1) * 8;

    for (int i = 0; i < NP; i++) {
        const int s = i % NPAIRS;
        asm volatile("cp.async.wait_group 1;" ::: "memory");
        __syncthreads();

        if (i + 2 < NP) load_pair((i + 2) % NPAIRS, i + 2);
        asm volatile("cp.async.commit_group;" ::: "memory");

        #pragma unroll
        for (int sub = 0; sub < 2; sub++) {
            const uint32_t baseA = sb + s * PAIR_B + sub * KT_B;
            const uint32_t baseB = baseA + TILE_B;
            #pragma unroll
            for (int ks = 0; ks < 2; ks++) {
                const int k16 = ks * 16;
                uint32_t af[2][4];
                #pragma unroll
                for (int mt = 0; mt < 2; mt++)
                    ldsm_x4(af[mt], baseA + swz(a_row + mt * 16, (k16 + a_col) * 2));
                uint32_t bf[8][2];
                #pragma unroll
                for (int np = 0; np < 4; np++) {
                    uint32_t r[4];
                    ldsm_x4(r, baseB + swz(b_row + np * 16, (k16 + b_col) * 2));
                    bf[np*2][0]   = r[0]; bf[np*2][1]   = r[1];
                    bf[np*2+1][0] = r[2]; bf[np*2+1][1] = r[3];
                }
                #pragma unroll
                for (int mt = 0; mt < 2; mt++)
                    #pragma unroll
                    for (int nt = 0; nt < 8; nt++)
                        mma_fp16(acc[mt][nt], af[mt], bf[nt]);
            }
        }
    }

    const int m_base = bm * BM + wm * 32 + (lane >> 2);
    const int n_base = bn * BN + wn * 64 + (lane & 3) * 2;
    #pragma unroll
    for (int mt = 0; mt < 2; mt++) {
        #pragma unroll
        for (int half = 0; half < 2; half++) {
            const int m = m_base + mt * 16 + half * 8;
            #pragma unroll
            for (int nt = 0; nt < 8; nt++) {
                const int n = n_base + nt * 8;
                float2 fv;
                fv.x = fmaxf(acc[mt][nt][half*2+0] + __ldg(&bias[n]),   0.f);
                fv.y = fmaxf(acc[mt][nt][half*2+1] + __ldg(&bias[n+1]), 0.f);
                *(float2*)(Of + (size_t)m * Nfull + n) = fv;
            }
        }
    }
}

// ---------------------------------------------------------------------------
// Final: out[b] = sigmoid( y2[b,:] . w3 + b3 )
// ---------------------------------------------------------------------------
__global__ __launch_bounds__(256) void final_kernel(
    const float* __restrict__ y2, const float* __restrict__ w3,
    const float* __restrict__ b3, float* __restrict__ out)
{
    __shared__ float sw[N2];
    const int tid = threadIdx.x;
    for (int i = tid; i < N2; i += 256) sw[i] = w3[i];
    __syncthreads();

    const int warp = tid >> 5, lane = tid & 31;
    const int row  = blockIdx.x * 8 + warp;
    const float* yr = y2 + (size_t)row * N2;

    float s = 0.f;
    #pragma unroll 4
    for (int k = lane; k < N2; k += 32) s = fmaf(yr[k], sw[k], s);
    #pragma unroll
    for (int o = 16; o; o >>= 1) s += __shfl_xor_sync(0xffffffffu, s, o);
    if (lane == 0) out[row] = 1.f / (1.f + expf(-(s + b3[0])));
}

// ---------------------------------------------------------------------------
extern "C" void kernel_launch(void* const* d_in, const int* in_sizes, int n_in,
                              void* d_out, int out_size)
{
    const float* emb   = (const float*)d_in[0];
    const float* bn_w  = (const float*)d_in[1];
    const float* bn_b  = (const float*)d_in[2];
    const float* bn_m  = (const float*)d_in[3];
    const float* bn_v  = (const float*)d_in[4];
    const float* se_w1 = (const float*)d_in[5];
    const float* se_w2 = (const float*)d_in[6];
    const float* w_bl  = (const float*)d_in[7];
    const float* d_w1  = (const float*)d_in[8];
    const float* d_b1  = (const float*)d_in[9];
    const float* d_w2  = (const float*)d_in[10];
    const float* d_b2  = (const float*)d_in[11];
    const float* d_w3  = (const float*)d_in[12];
    const float* d_b3  = (const float*)d_in[13];
    float* out = (float*)d_out;

    __half *h, *w1, *y1, *w2;
    float *y2, *p0, *p1;
    cudaGetSymbolAddress((void**)&h,  g_h);
    cudaGetSymbolAddress((void**)&w1, g_w1);
    cudaGetSymbolAddress((void**)&y1, g_y1);
    cudaGetSymbolAddress((void**)&w2, g_w2);
    cudaGetSymbolAddress((void**)&y2, g_y2);
    cudaGetSymbolAddress((void**)&p0, g_p0);
    cudaGetSymbolAddress((void**)&p1, g_p1);

    cudaFuncSetAttribute(gemm1_sk,  cudaFuncAttributeMaxDynamicSharedMemorySize, GEMM_SMEM);
    cudaFuncSetAttribute(gemm_fp16, cudaFuncAttributeMaxDynamicSharedMemorySize, GEMM_SMEM);

    // 1) feature construction (fp16)
    feat_kernel<<<B_SZ, 256>>>(emb, bn_w, bn_b, bn_m, bn_v, se_w1, se_w2, w_bl, h);

    // 2) weight converts (vectorized; sizes divisible by 4)
    split_kernel<<<4096, 256>>>(d_w1, w1, (size_t)N1 * K1 / 4);
    split_kernel<<<512,  256>>>(d_w2, w2, (size_t)N2 * N1 / 4);

    // 3) GEMM1 stream-K: [8192,12480] x [1024,12480]^T + relu -> y1 (fp16)
    gemm1_sk<<<NCTA1, 256, GEMM_SMEM>>>(h, w1, d_b1, y1, p0, p1);
    gemm1_fix<<<NT1, 256>>>(p0, p1, d_b1, y1);

    // 4) GEMM2: [8192,1024] x [512,1024]^T + relu -> y2 (fp32)
    dim3 g2(N2 / BN, B_SZ / BM);
    gemm_fp16<<<g2, 256, GEMM_SMEM>>>(y1, w2, d_b2, y2, N2, N1);

    // 5) GEMV + sigmoid
    final_kernel<<<B_SZ / 8, 256>>>(y2, d_w3, d_b3, out);
}

// round 15
// speedup vs baseline: 1.0440x; 1.0440x over previous
#include <cuda_runtime.h>
#include <cuda_fp16.h>
#include <stdint.h>
#include <math.h>

#define B_SZ 8192
#define F    40
#define E    8
#define FE   320
#define RDIM 5
#define P    780
#define K1   12480
#define N1   1024
#define N2   512

// ---- GEMM tiling ----
#define BM 128
#define BN 128
#define BK 32
#define TILE_B 8192                      // one matrix tile: 128 rows x 64B swizzled
#define STAGE_B (2 * TILE_B)             // A + B = 16KB
#define NSTAGE 6
#define GEMM_SMEM (NSTAGE * STAGE_B)     // 98304 -> 2 CTAs/SM

// ---- stream-K for GEMM1 ----
#define NKT1  (K1 / BK)                  // 390 kt per tile
#define NTM1  (B_SZ / BM)                // 64
#define NTN1  (N1 / BN)                  // 8
#define NT1   (NTM1 * NTN1)              // 512 tiles
#define NCTA1 296                        // 148 SMs x 2 CTAs
#define U1    ((size_t)NT1 * NKT1)       // 199680 work units

// -------------------- device scratch --------------------
__device__ __half g_h [(size_t)B_SZ * K1];
__device__ __half g_w1[(size_t)N1 * K1];
__device__ __half g_y1[(size_t)B_SZ * N1];
__device__ __half g_w2[(size_t)N2 * N1];
__device__ float  g_y2[(size_t)B_SZ * N2];
__device__ float  g_p0[(size_t)NT1 * BM * BN];   // stream-K partial (k-head)
__device__ float  g_p1[(size_t)NT1 * BM * BN];   // stream-K partial (k-tail)

// -------------------- helpers --------------------
__device__ __forceinline__ uint32_t smem_u32(const void* p) {
    uint32_t a;
    asm("{ .reg .u64 t; cvta.to.shared.u64 t, %1; cvt.u32.u64 %0, t; }" : "=r"(a) : "l"(p));
    return a;
}
__device__ __forceinline__ void cp16(uint32_t dst, const void* src) {
    asm volatile("cp.async.cg.shared.global [%0], [%1], 16;" :: "r"(dst), "l"(src));
}
__device__ __forceinline__ void ldsm_x4(uint32_t* r, uint32_t addr) {
    asm volatile("ldmatrix.sync.aligned.m8n8.x4.shared.b16 {%0,%1,%2,%3}, [%4];"
                 : "=r"(r[0]), "=r"(r[1]), "=r"(r[2]), "=r"(r[3]) : "r"(addr));
}
__device__ __forceinline__ void mma_fp16(float* c, const uint32_t* a, const uint32_t* b) {
    asm volatile(
        "mma.sync.aligned.m16n8k16.row.col.f32.f16.f16.f32 "
        "{%0,%1,%2,%3}, {%4,%5,%6,%7}, {%8,%9}, {%0,%1,%2,%3};"
        : "+f"(c[0]), "+f"(c[1]), "+f"(c[2]), "+f"(c[3])
        : "r"(a[0]), "r"(a[1]), "r"(a[2]), "r"(a[3]), "r"(b[0]), "r"(b[1]));
}
// swizzled byte offset within an 8KB tile: row r (0..127), byte col bc (0..63, 16B-aligned)
__device__ __forceinline__ uint32_t swz(int r, int bc) {
    return (uint32_t)(r * 64 + ((((bc) >> 4) ^ ((r >> 1) & 3)) << 4));
}
__device__ __forceinline__ uint32_t pack2h(float a, float b) {
    __half2 h = __floats2half2_rn(a, b);
    return *(uint32_t*)&h;
}

// ---------------------------------------------------------------------------
// Kernel A: BN + SENet + bilinear -> h (fp16), vectorized 16B stores.
// ---------------------------------------------------------------------------
__global__ __launch_bounds__(256) void feat_kernel(
    const float* __restrict__ emb,  const float* __restrict__ bn_w,
    const float* __restrict__ bn_b, const float* __restrict__ bn_m,
    const float* __restrict__ bn_v, const float* __restrict__ se_w1,
    const float* __restrict__ se_w2,const float* __restrict__ w_bl,
    __half* __restrict__ h_out)
{
    __shared__ float sV[FE], sT[FE], sZ[F], sH[RDIM], sA[F], sW[E*E];
    __shared__ unsigned char s_pi[P], s_pj[P];

    const int tid = threadIdx.x;
    const int b   = blockIdx.x;

    if (tid == 0) {
        int p = 0;
        for (int i = 0; i < F; i++)
            for (int j = i + 1; j < F; j++) { s_pi[p] = (unsigned char)i; s_pj[p] = (unsigned char)j; p++; }
    }
    if (tid < E*E) sW[tid] = w_bl[tid];

    for (int idx = tid; idx < FE; idx += 256) {
        float x   = emb[(size_t)b * FE + idx];
        float inv = rsqrtf(bn_v[idx] + 1e-5f);
        sV[idx]   = (x - bn_m[idx]) * inv * bn_w[idx] + bn_b[idx];
    }
    __syncthreads();

    if (tid < F) {
        float s = 0.f;
        #pragma unroll
        for (int e = 0; e < E; e++) s += sV[tid * E + e];
        sZ[tid] = s * (1.f / E);
    }
    __syncthreads();

    if (tid < RDIM) {
        float s = 0.f;
        #pragma unroll
        for (int f = 0; f < F; f++) s += sZ[f] * se_w1[tid * F + f];
        sH[tid] = fmaxf(s, 0.f);
    }
    __syncthreads();

    if (tid < F) {
        float s = 0.f;
        #pragma unroll
        for (int r = 0; r < RDIM; r++) s += sH[r] * se_w2[tid * RDIM + r];
        sA[tid] = fmaxf(s, 0.f);
    }

    for (int idx = tid; idx < FE; idx += 256) {
        int f = idx >> 3, d = idx & 7;
        float s = 0.f;
        #pragma unroll
        for (int e = 0; e < E; e++) s += sV[f * E + e] * sW[d * E + e];
        sT[idx] = s;
    }
    __syncthreads();

    __half* oh = h_out + (size_t)b * K1;
    for (int g = tid; g < 2 * P; g += 256) {
        const int p = (g < P) ? g : (g - P);
        const int i = s_pi[p], j = s_pj[p];
        const float sc = (g < P) ? (sA[i] * sA[j]) : 1.f;
        const float4 ta = *(const float4*)&sT[i * E];
        const float4 tb = *(const float4*)&sT[i * E + 4];
        const float4 va = *(const float4*)&sV[j * E];
        const float4 vb = *(const float4*)&sV[j * E + 4];
        uint4 hv;
        hv.x = pack2h((ta.x * va.x) * sc, (ta.y * va.y) * sc);
        hv.y = pack2h((ta.z * va.z) * sc, (ta.w * va.w) * sc);
        hv.z = pack2h((tb.x * vb.x) * sc, (tb.y * vb.y) * sc);
        hv.w = pack2h((tb.z * vb.z) * sc, (tb.w * vb.w) * sc);
        *(uint4*)(oh + (size_t)g * 8) = hv;
    }
}

// ---------------------------------------------------------------------------
// Weight convert fp32 -> fp16, vectorized (n4 = n/4)
// ---------------------------------------------------------------------------
__global__ __launch_bounds__(256) void split_kernel(
    const float* __restrict__ src, __half* __restrict__ dst, size_t n4)
{
    for (size_t i = (size_t)blockIdx.x * blockDim.x + threadIdx.x; i < n4;
         i += (size_t)gridDim.x * blockDim.x) {
        float4 v = ((const float4*)src)[i];
        uint2 hv;
        hv.x = pack2h(v.x, v.y);
        hv.y = pack2h(v.z, v.w);
        *(uint2*)(dst + i * 4) = hv;
    }
}

// ---------------------------------------------------------------------------
// GEMM1 stream-K phase 1 (fp16): 296 persistent CTAs.
// 6-stage cp.async pipeline (lookahead 5 kt), single barrier per kt.
// ---------------------------------------------------------------------------
__global__ void __launch_bounds__(256, 2) gemm1_sk(
    const __half* __restrict__ A, const __half* __restrict__ B,
    const float* __restrict__ bias,
    __half* __restrict__ Oh,
    float* __restrict__ p0, float* __restrict__ p1)
{
    extern __shared__ char smem[];
    const uint32_t sb  = smem_u32(smem);
    const int tid  = threadIdx.x;
    const int warp = tid >> 5, lane = tid & 31;
    const int wm   = warp & 3;
    const int wn   = warp >> 2;

    // per-thread load coords (2 x 16B chunks per matrix per kt)
    const int r0 = tid >> 2, c0 = tid & 3;
    const uint32_t s_off0 = swz(r0, c0 * 16);
    const uint32_t s_off1 = swz(r0 + 64, c0 * 16);
    const size_t rowK  = (size_t)K1 * 2;
    const size_t g_off0 = (size_t)r0 * rowK + c0 * 16;
    const size_t g_off1 = (size_t)(r0 + 64) * rowK + c0 * 16;

    // ldmatrix lane coords (tile-local)
    const int a_row = wm * 32 + (lane & 15);
    const int a_col = (lane >> 4) * 8;
    const int b_row = wn * 64 + ((lane >> 4) << 3) + (lane & 7);
    const int b_col = ((lane >> 3) & 1) * 8;

    size_t beg = (size_t)blockIdx.x       * U1 / NCTA1;
    size_t end = (size_t)(blockIdx.x + 1) * U1 / NCTA1;

    bool first_seg = true;
    while (beg < end) {
        const int t  = (int)(beg / NKT1);
        const int k0 = (int)(beg % NKT1);
        int L = NKT1 - k0;
        if ((size_t)L > end - beg) L = (int)(end - beg);
        const int bm = t >> 3, bn = t & 7;

        const char* pA = (const char*)(A + (size_t)bm * BM * K1);
        const char* pB = (const char*)(B + (size_t)bn * BN * K1);

        float acc[2][8][4];
        #pragma unroll
        for (int i = 0; i < 2; i++)
            #pragma unroll
            for (int j = 0; j < 8; j++)
                #pragma unroll
                for (int r = 0; r < 4; r++) acc[i][j][r] = 0.f;

        auto load_stage = [&](int s, int kt) {
            const uint32_t base = sb + s * STAGE_B;
            const size_t koff = (size_t)kt * (BK * 2);
            cp16(base + s_off0,          pA + g_off0 + koff);
            cp16(base + s_off1,          pA + g_off1 + koff);
            cp16(base + TILE_B + s_off0, pB + g_off0 + koff);
            cp16(base + TILE_B + s_off1, pB + g_off1 + koff);
        };

        // barrier between segments: last ldsm of prev segment vs new writes
        if (!first_seg) __syncthreads();
        first_seg = false;

        #pragma unroll
        for (int pf = 0; pf < NSTAGE - 1; pf++) {
            if (pf < L) load_stage(pf, k0 + pf);
            asm volatile("cp.async.commit_group;" ::: "memory");
        }

        int s = 0, sn = NSTAGE - 1;   // current stage, prefetch stage (ring)
        for (int i = 0; i < L; i++) {
            asm volatile("cp.async.wait_group 4;" ::: "memory");
            __syncthreads();

            if (i + NSTAGE - 1 < L) load_stage(sn, k0 + i + NSTAGE - 1);
            asm volatile("cp.async.commit_group;" ::: "memory");

            const uint32_t baseA = sb + s * STAGE_B;
            const uint32_t baseB = baseA + TILE_B;

            #pragma unroll
            for (int ks = 0; ks < 2; ks++) {
                const int k16 = ks * 16;
                uint32_t af[2][4];
                #pragma unroll
                for (int mt = 0; mt < 2; mt++)
                    ldsm_x4(af[mt], baseA + swz(a_row + mt * 16, (k16 + a_col) * 2));
                uint32_t bf[8][2];
                #pragma unroll
                for (int np = 0; np < 4; np++) {
                    uint32_t r[4];
                    ldsm_x4(r, baseB + swz(b_row + np * 16, (k16 + b_col) * 2));
                    bf[np*2][0]   = r[0]; bf[np*2][1]   = r[1];
                    bf[np*2+1][0] = r[2]; bf[np*2+1][1] = r[3];
                }
                #pragma unroll
                for (int mt = 0; mt < 2; mt++)
                    #pragma unroll
                    for (int nt = 0; nt < 8; nt++)
                        mma_fp16(acc[mt][nt], af[mt], bf[nt]);
            }

            if (++s == NSTAGE) s = 0;
            if (++sn == NSTAGE) sn = 0;
        }
        asm volatile("cp.async.wait_group 0;" ::: "memory");

        // ---- epilogue for this segment ----
        const bool full = (k0 == 0) && (L == NKT1);
        const int ml0 = wm * 32 + (lane >> 2);
        const int nl0 = wn * 64 + (lane & 3) * 2;
        if (full) {
            #pragma unroll
            for (int mt = 0; mt < 2; mt++)
                #pragma unroll
                for (int half = 0; half < 2; half++) {
                    const int m = bm * BM + ml0 + mt * 16 + half * 8;
                    #pragma unroll
                    for (int nt = 0; nt < 8; nt++) {
                        const int n = bn * BN + nl0 + nt * 8;
                        float v0 = fmaxf(acc[mt][nt][half*2+0] + __ldg(&bias[n]),   0.f);
                        float v1 = fmaxf(acc[mt][nt][half*2+1] + __ldg(&bias[n+1]), 0.f);
                        *(uint32_t*)(Oh + (size_t)m * N1 + n) = pack2h(v0, v1);
                    }
                }
        } else {
            float* pp = ((k0 == 0) ? p0 : p1) + (size_t)t * (BM * BN);
            #pragma unroll
            for (int mt = 0; mt < 2; mt++)
                #pragma unroll
                for (int half = 0; half < 2; half++) {
                    const int ml = ml0 + mt * 16 + half * 8;
                    #pragma unroll
                    for (int nt = 0; nt < 8; nt++) {
                        const int nl = nl0 + nt * 8;
                        float2 fv;
                        fv.x = acc[mt][nt][half*2+0];
                        fv.y = acc[mt][nt][half*2+1];
                        *(float2*)(pp + ml * BN + nl) = fv;
                    }
                }
        }
        beg += L;
    }
}

// ---------------------------------------------------------------------------
// GEMM1 stream-K phase 2: combine partials for split tiles (deterministic).
// ---------------------------------------------------------------------------
__global__ __launch_bounds__(256) void gemm1_fix(
    const float* __restrict__ p0, const float* __restrict__ p1,
    const float* __restrict__ bias,
    __half* __restrict__ Oh)
{
    const int t = blockIdx.x;
    const unsigned long long lo = (unsigned long long)t * NKT1;
    unsigned long long c = ((lo + 1) * NCTA1 + U1 - 1) / U1;
    if (c < 1 || c > NCTA1 - 1) return;
    unsigned long long bnd = c * U1 / NCTA1;
    if (bnd >= lo + NKT1) return;   // no interior boundary -> tile was whole

    const int bm = t >> 3, bn = t & 7;
    const float* a = p0 + (size_t)t * (BM * BN);
    const float* b = p1 + (size_t)t * (BM * BN);

    #pragma unroll 4
    for (int j = 0; j < (BM * BN) / 256; j++) {
        const int idx = threadIdx.x + j * 256;
        const int ml = idx >> 7, nl = idx & 127;
        const int n = bn * BN + nl;
        float v = fmaxf(a[idx] + b[idx] + bias[n], 0.f);
        Oh[(size_t)(bm * BM + ml) * N1 + n] = __float2half_rn(v);
    }
}

// ---------------------------------------------------------------------------
// GEMM2 (fp16, NT), classic tiled, 6-stage pipeline, writes fp32.
// ---------------------------------------------------------------------------
__global__ void __launch_bounds__(256, 2) gemm_fp16(
    const __half* __restrict__ A, const __half* __restrict__ B,
    const float* __restrict__ bias,
    float* __restrict__ Of,
    int Nfull, int K)
{
    extern __shared__ char smem[];
    const uint32_t sb  = smem_u32(smem);
    const int tid  = threadIdx.x;
    const int warp = tid >> 5, lane = tid & 31;
    const int wm   = warp & 3;
    const int wn   = warp >> 2;
    const int bn   = blockIdx.x, bm = blockIdx.y;
    const int nkt  = K / BK;

    const char* pA = (const char*)(A + (size_t)bm * BM * K);
    const char* pB = (const char*)(B + (size_t)bn * BN * K);
    const size_t rowK = (size_t)K * 2;

    const int r0 = tid >> 2, c0 = tid & 3;
    const uint32_t s_off0 = swz(r0, c0 * 16);
    const uint32_t s_off1 = swz(r0 + 64, c0 * 16);
    const size_t  g_off0 = (size_t)r0 * rowK + c0 * 16;
    const size_t  g_off1 = (size_t)(r0 + 64) * rowK + c0 * 16;

    auto load_stage = [&](int s, int kt) {
        const uint32_t base = sb + s * STAGE_B;
        const size_t koff = (size_t)kt * (BK * 2);
        cp16(base + s_off0,          pA + g_off0 + koff);
        cp16(base + s_off1,          pA + g_off1 + koff);
        cp16(base + TILE_B + s_off0, pB + g_off0 + koff);
        cp16(base + TILE_B + s_off1, pB + g_off1 + koff);
    };

    float acc[2][8][4];
    #pragma unroll
    for (int i = 0; i < 2; i++)
        #pragma unroll
        for (int j = 0; j < 8; j++)
            #pragma unroll
            for (int r = 0; r < 4; r++) acc[i][j][r] = 0.f;

    #pragma unroll
    for (int pf = 0; pf < NSTAGE - 1; pf++) {
        if (pf < nkt) load_stage(pf, pf);
        asm volatile("cp.async.commit_group;" ::: "memory");
    }

    const int a_row = wm * 32 + (lane & 15);
    const int a_col = (lane >> 4) * 8;
    const int b_row = wn * 64 + ((lane >> 4) << 3) + (lane & 7);
    const int b_col = ((lane >> 3) & 1) * 8;

    int s = 0, sn = NSTAGE - 1;
    for (int kt = 0; kt < nkt; kt++) {
        asm volatile("cp.async.wait_group 4;" ::: "memory");
        __syncthreads();

        if (kt + NSTAGE - 1 < nkt) load_stage(sn, kt + NSTAGE - 1);
        asm volatile("cp.async.commit_group;" ::: "memory");

        const uint32_t baseA = sb + s * STAGE_B;
        const uint32_t baseB = baseA + TILE_B;

        #pragma unroll
        for (int ks = 0; ks < 2; ks++) {
            const int k16 = ks * 16;
            uint32_t af[2][4];
            #pragma unroll
            for (int mt = 0; mt < 2; mt++)
                ldsm_x4(af[mt], baseA + swz(a_row + mt * 16, (k16 + a_col) * 2));
            uint32_t bf[8][2];
            #pragma unroll
            for (int np = 0; np < 4; np++) {
                uint32_t r[4];
                ldsm_x4(r, baseB + swz(b_row + np * 16, (k16 + b_col) * 2));
                bf[np*2][0]   = r[0]; bf[np*2][1]   = r[1];
                bf[np*2+1][0] = r[2]; bf[np*2+1][1] = r[3];
            }
            #pragma unroll
            for (int mt = 0; mt < 2; mt++)
                #pragma unroll
                for (int nt = 0; nt < 8; nt++)
                    mma_fp16(acc[mt][nt], af[mt], bf[nt]);
        }

        if (++s == NSTAGE) s = 0;
        if (++sn == NSTAGE) sn = 0;
    }

    const int m_base = bm * BM + wm * 32 + (lane >> 2);
    const int n_base = bn * BN + wn * 64 + (lane & 3) * 2;
    #pragma unroll
    for (int mt = 0; mt < 2; mt++) {
        #pragma unroll
        for (int half = 0; half < 2; half++) {
            const int m = m_base + mt * 16 + half * 8;
            #pragma unroll
            for (int nt = 0; nt < 8; nt++) {
                const int n = n_base + nt * 8;
                float2 fv;
                fv.x = fmaxf(acc[mt][nt][half*2+0] + __ldg(&bias[n]),   0.f);
                fv.y = fmaxf(acc[mt][nt][half*2+1] + __ldg(&bias[n+1]), 0.f);
                *(float2*)(Of + (size_t)m * Nfull + n) = fv;
            }
        }
    }
}

// ---------------------------------------------------------------------------
// Final: out[b] = sigmoid( y2[b,:] . w3 + b3 )
// ---------------------------------------------------------------------------
__global__ __launch_bounds__(256) void final_kernel(
    const float* __restrict__ y2, const float* __restrict__ w3,
    const float* __restrict__ b3, float* __restrict__ out)
{
    __shared__ float sw[N2];
    const int tid = threadIdx.x;
    for (int i = tid; i < N2; i += 256) sw[i] = w3[i];
    __syncthreads();

    const int warp = tid >> 5, lane = tid & 31;
    const int row  = blockIdx.x * 8 + warp;
    const float* yr = y2 + (size_t)row * N2;

    float s = 0.f;
    #pragma unroll 4
    for (int k = lane; k < N2; k += 32) s = fmaf(yr[k], sw[k], s);
    #pragma unroll
    for (int o = 16; o; o >>= 1) s += __shfl_xor_sync(0xffffffffu, s, o);
    if (lane == 0) out[row] = 1.f / (1.f + expf(-(s + b3[0])));
}

// ---------------------------------------------------------------------------
extern "C" void kernel_launch(void* const* d_in, const int* in_sizes, int n_in,
                              void* d_out, int out_size)
{
    const float* emb   = (const float*)d_in[0];
    const float* bn_w  = (const float*)d_in[1];
    const float* bn_b  = (const float*)d_in[2];
    const float* bn_m  = (const float*)d_in[3];
    const float* bn_v  = (const float*)d_in[4];
    const float* se_w1 = (const float*)d_in[5];
    const float* se_w2 = (const float*)d_in[6];
    const float* w_bl  = (const float*)d_in[7];
    const float* d_w1  = (const float*)d_in[8];
    const float* d_b1  = (const float*)d_in[9];
    const float* d_w2  = (const float*)d_in[10];
    const float* d_b2  = (const float*)d_in[11];
    const float* d_w3  = (const float*)d_in[12];
    const float* d_b3  = (const float*)d_in[13];
    float* out = (float*)d_out;

    __half *h, *w1, *y1, *w2;
    float *y2, *p0, *p1;
    cudaGetSymbolAddress((void**)&h,  g_h);
    cudaGetSymbolAddress((void**)&w1, g_w1);
    cudaGetSymbolAddress((void**)&y1, g_y1);
    cudaGetSymbolAddress((void**)&w2, g_w2);
    cudaGetSymbolAddress((void**)&y2, g_y2);
    cudaGetSymbolAddress((void**)&p0, g_p0);
    cudaGetSymbolAddress((void**)&p1, g_p1);

    cudaFuncSetAttribute(gemm1_sk,  cudaFuncAttributeMaxDynamicSharedMemorySize, GEMM_SMEM);
    cudaFuncSetAttribute(gemm_fp16, cudaFuncAttributeMaxDynamicSharedMemorySize, GEMM_SMEM);

    // 1) feature construction (fp16)
    feat_kernel<<<B_SZ, 256>>>(emb, bn_w, bn_b, bn_m, bn_v, se_w1, se_w2, w_bl, h);

    // 2) weight converts (vectorized; sizes divisible by 4)
    split_kernel<<<4096, 256>>>(d_w1, w1, (size_t)N1 * K1 / 4);
    split_kernel<<<512,  256>>>(d_w2, w2, (size_t)N2 * N1 / 4);

    // 3) GEMM1 stream-K: [8192,12480] x [1024,12480]^T + relu -> y1 (fp16)
    gemm1_sk<<<NCTA1, 256, GEMM_SMEM>>>(h, w1, d_b1, y1, p0, p1);
    gemm1_fix<<<NT1, 256>>>(p0, p1, d_b1, y1);

    // 4) GEMM2: [8192,1024] x [512,1024]^T + relu -> y2 (fp32)
    dim3 g2(N2 / BN, B_SZ / BM);
    gemm_fp16<<<g2, 256, GEMM_SMEM>>>(y1, w2, d_b2, y2, N2, N1);

    // 5) GEMV + sigmoid
    final_kernel<<<B_SZ / 8, 256>>>(y2, d_w3, d_b3, out);
}

// round 16
// speedup vs baseline: 1.0444x; 1.0004x over previous
#include <cuda_runtime.h>
#include <cuda_fp16.h>
#include <stdint.h>
#include <math.h>

#define B_SZ 8192
#define F    40
#define E    8
#define FE   320
#define RDIM 5
#define P    780
#define K1   12480
#define N1   1024
#define N2   512

// ---- GEMM tiling ----
#define BM 128
#define BN 128
#define BK 32
#define TILE_B 8192                      // one matrix tile: 128 rows x 64B swizzled
#define STAGE_B (2 * TILE_B)             // A + B = 16KB
#define NSTAGE 6
#define GEMM_SMEM (NSTAGE * STAGE_B)     // 98304 -> 2 CTAs/SM

// ---- stream-K for GEMM1 ----
#define NKT1  (K1 / BK)                  // 390 kt per tile
#define NTM1  (B_SZ / BM)                // 64
#define NTN1  (N1 / BN)                  // 8
#define NT1   (NTM1 * NTN1)              // 512 tiles
#define NCTA1 296                        // 148 SMs x 2 CTAs
#define U1    ((size_t)NT1 * NKT1)       // 199680 work units

// -------------------- device scratch --------------------
__device__ __half g_h [(size_t)B_SZ * K1];
__device__ __half g_w1[(size_t)N1 * K1];
__device__ __half g_y1[(size_t)B_SZ * N1];
__device__ __half g_w2[(size_t)N2 * N1];
__device__ float  g_part[(size_t)B_SZ * 8];      // fused GEMM2+GEMV partials
__device__ float  g_p0[(size_t)NT1 * BM * BN];   // stream-K partial (k-head)
__device__ float  g_p1[(size_t)NT1 * BM * BN];   // stream-K partial (k-tail)

// -------------------- helpers --------------------
__device__ __forceinline__ uint32_t smem_u32(const void* p) {
    uint32_t a;
    asm("{ .reg .u64 t; cvta.to.shared.u64 t, %1; cvt.u32.u64 %0, t; }" : "=r"(a) : "l"(p));
    return a;
}
__device__ __forceinline__ void cp16(uint32_t dst, const void* src) {
    asm volatile("cp.async.cg.shared.global [%0], [%1], 16;" :: "r"(dst), "l"(src));
}
__device__ __forceinline__ void ldsm_x4(uint32_t* r, uint32_t addr) {
    asm volatile("ldmatrix.sync.aligned.m8n8.x4.shared.b16 {%0,%1,%2,%3}, [%4];"
                 : "=r"(r[0]), "=r"(r[1]), "=r"(r[2]), "=r"(r[3]) : "r"(addr));
}
__device__ __forceinline__ void mma_fp16(float* c, const uint32_t* a, const uint32_t* b) {
    asm volatile(
        "mma.sync.aligned.m16n8k16.row.col.f32.f16.f16.f32 "
        "{%0,%1,%2,%3}, {%4,%5,%6,%7}, {%8,%9}, {%0,%1,%2,%3};"
        : "+f"(c[0]), "+f"(c[1]), "+f"(c[2]), "+f"(c[3])
        : "r"(a[0]), "r"(a[1]), "r"(a[2]), "r"(a[3]), "r"(b[0]), "r"(b[1]));
}
// swizzled byte offset within an 8KB tile: row r (0..127), byte col bc (0..63, 16B-aligned)
__device__ __forceinline__ uint32_t swz(int r, int bc) {
    return (uint32_t)(r * 64 + ((((bc) >> 4) ^ ((r >> 1) & 3)) << 4));
}
__device__ __forceinline__ uint32_t pack2h(float a, float b) {
    __half2 h = __floats2half2_rn(a, b);
    return *(uint32_t*)&h;
}

// ---------------------------------------------------------------------------
// Kernel A: BN + SENet + bilinear -> h (fp16), vectorized 16B stores.
// ---------------------------------------------------------------------------
__global__ __launch_bounds__(256) void feat_kernel(
    const float* __restrict__ emb,  const float* __restrict__ bn_w,
    const float* __restrict__ bn_b, const float* __restrict__ bn_m,
    const float* __restrict__ bn_v, const float* __restrict__ se_w1,
    const float* __restrict__ se_w2,const float* __restrict__ w_bl,
    __half* __restrict__ h_out)
{
    __shared__ float sV[FE], sT[FE], sZ[F], sH[RDIM], sA[F], sW[E*E];
    __shared__ unsigned char s_pi[P], s_pj[P];

    const int tid = threadIdx.x;
    const int b   = blockIdx.x;

    if (tid == 0) {
        int p = 0;
        for (int i = 0; i < F; i++)
            for (int j = i + 1; j < F; j++) { s_pi[p] = (unsigned char)i; s_pj[p] = (unsigned char)j; p++; }
    }
    if (tid < E*E) sW[tid] = w_bl[tid];

    for (int idx = tid; idx < FE; idx += 256) {
        float x   = emb[(size_t)b * FE + idx];
        float inv = rsqrtf(bn_v[idx] + 1e-5f);
        sV[idx]   = (x - bn_m[idx]) * inv * bn_w[idx] + bn_b[idx];
    }
    __syncthreads();

    if (tid < F) {
        float s = 0.f;
        #pragma unroll
        for (int e = 0; e < E; e++) s += sV[tid * E + e];
        sZ[tid] = s * (1.f / E);
    }
    __syncthreads();

    if (tid < RDIM) {
        float s = 0.f;
        #pragma unroll
        for (int f = 0; f < F; f++) s += sZ[f] * se_w1[tid * F + f];
        sH[tid] = fmaxf(s, 0.f);
    }
    __syncthreads();

    if (tid < F) {
        float s = 0.f;
        #pragma unroll
        for (int r = 0; r < RDIM; r++) s += sH[r] * se_w2[tid * RDIM + r];
        sA[tid] = fmaxf(s, 0.f);
    }

    for (int idx = tid; idx < FE; idx += 256) {
        int f = idx >> 3, d = idx & 7;
        float s = 0.f;
        #pragma unroll
        for (int e = 0; e < E; e++) s += sV[f * E + e] * sW[d * E + e];
        sT[idx] = s;
    }
    __syncthreads();

    __half* oh = h_out + (size_t)b * K1;
    for (int g = tid; g < 2 * P; g += 256) {
        const int p = (g < P) ? g : (g - P);
        const int i = s_pi[p], j = s_pj[p];
        const float sc = (g < P) ? (sA[i] * sA[j]) : 1.f;
        const float4 ta = *(const float4*)&sT[i * E];
        const float4 tb = *(const float4*)&sT[i * E + 4];
        const float4 va = *(const float4*)&sV[j * E];
        const float4 vb = *(const float4*)&sV[j * E + 4];
        uint4 hv;
        hv.x = pack2h((ta.x * va.x) * sc, (ta.y * va.y) * sc);
        hv.y = pack2h((ta.z * va.z) * sc, (ta.w * va.w) * sc);
        hv.z = pack2h((tb.x * vb.x) * sc, (tb.y * vb.y) * sc);
        hv.w = pack2h((tb.z * vb.z) * sc, (tb.w * vb.w) * sc);
        *(uint4*)(oh + (size_t)g * 8) = hv;
    }
}

// ---------------------------------------------------------------------------
// Weight convert fp32 -> fp16, both weight matrices in one launch.
// ---------------------------------------------------------------------------
#define W1_Q ((size_t)N1 * K1 / 4)
#define W2_Q ((size_t)N2 * N1 / 4)
__global__ __launch_bounds__(256) void split_kernel(
    const float* __restrict__ s1, __half* __restrict__ d1,
    const float* __restrict__ s2, __half* __restrict__ d2)
{
    const size_t total = W1_Q + W2_Q;
    for (size_t i = (size_t)blockIdx.x * blockDim.x + threadIdx.x; i < total;
         i += (size_t)gridDim.x * blockDim.x) {
        const float* src = (i < W1_Q) ? s1 : s2;
        __half*      dst = (i < W1_Q) ? d1 : d2;
        const size_t j   = (i < W1_Q) ? i : (i - W1_Q);
        float4 v = ((const float4*)src)[j];
        uint2 hv;
        hv.x = pack2h(v.x, v.y);
        hv.y = pack2h(v.z, v.w);
        *(uint2*)(dst + j * 4) = hv;
    }
}

// ---------------------------------------------------------------------------
// GEMM1 stream-K phase 1 (fp16): 296 persistent CTAs.
// 6-stage cp.async pipeline (lookahead 5 kt), single barrier per kt.
// ---------------------------------------------------------------------------
__global__ void __launch_bounds__(256, 2) gemm1_sk(
    const __half* __restrict__ A, const __half* __restrict__ B,
    const float* __restrict__ bias,
    __half* __restrict__ Oh,
    float* __restrict__ p0, float* __restrict__ p1)
{
    extern __shared__ char smem[];
    const uint32_t sb  = smem_u32(smem);
    const int tid  = threadIdx.x;
    const int warp = tid >> 5, lane = tid & 31;
    const int wm   = warp & 3;
    const int wn   = warp >> 2;

    // per-thread load coords (2 x 16B chunks per matrix per kt)
    const int r0 = tid >> 2, c0 = tid & 3;
    const uint32_t s_off0 = swz(r0, c0 * 16);
    const uint32_t s_off1 = swz(r0 + 64, c0 * 16);
    const size_t rowK  = (size_t)K1 * 2;
    const size_t g_off0 = (size_t)r0 * rowK + c0 * 16;
    const size_t g_off1 = (size_t)(r0 + 64) * rowK + c0 * 16;

    // ldmatrix lane coords (tile-local)
    const int a_row = wm * 32 + (lane & 15);
    const int a_col = (lane >> 4) * 8;
    const int b_row = wn * 64 + ((lane >> 4) << 3) + (lane & 7);
    const int b_col = ((lane >> 3) & 1) * 8;

    size_t beg = (size_t)blockIdx.x       * U1 / NCTA1;
    size_t end = (size_t)(blockIdx.x + 1) * U1 / NCTA1;

    bool first_seg = true;
    while (beg < end) {
        const int t  = (int)(beg / NKT1);
        const int k0 = (int)(beg % NKT1);
        int L = NKT1 - k0;
        if ((size_t)L > end - beg) L = (int)(end - beg);
        const int bm = t >> 3, bn = t & 7;

        const char* pA = (const char*)(A + (size_t)bm * BM * K1);
        const char* pB = (const char*)(B + (size_t)bn * BN * K1);

        float acc[2][8][4];
        #pragma unroll
        for (int i = 0; i < 2; i++)
            #pragma unroll
            for (int j = 0; j < 8; j++)
                #pragma unroll
                for (int r = 0; r < 4; r++) acc[i][j][r] = 0.f;

        auto load_stage = [&](int s, int kt) {
            const uint32_t base = sb + s * STAGE_B;
            const size_t koff = (size_t)kt * (BK * 2);
            cp16(base + s_off0,          pA + g_off0 + koff);
            cp16(base + s_off1,          pA + g_off1 + koff);
            cp16(base + TILE_B + s_off0, pB + g_off0 + koff);
            cp16(base + TILE_B + s_off1, pB + g_off1 + koff);
        };

        // barrier between segments: last ldsm of prev segment vs new writes
        if (!first_seg) __syncthreads();
        first_seg = false;

        #pragma unroll
        for (int pf = 0; pf < NSTAGE - 1; pf++) {
            if (pf < L) load_stage(pf, k0 + pf);
            asm volatile("cp.async.commit_group;" ::: "memory");
        }

        int s = 0, sn = NSTAGE - 1;   // current stage, prefetch stage (ring)
        for (int i = 0; i < L; i++) {
            asm volatile("cp.async.wait_group 4;" ::: "memory");
            __syncthreads();

            if (i + NSTAGE - 1 < L) load_stage(sn, k0 + i + NSTAGE - 1);
            asm volatile("cp.async.commit_group;" ::: "memory");

            const uint32_t baseA = sb + s * STAGE_B;
            const uint32_t baseB = baseA + TILE_B;

            #pragma unroll
            for (int ks = 0; ks < 2; ks++) {
                const int k16 = ks * 16;
                uint32_t af[2][4];
                #pragma unroll
                for (int mt = 0; mt < 2; mt++)
                    ldsm_x4(af[mt], baseA + swz(a_row + mt * 16, (k16 + a_col) * 2));
                uint32_t bf[8][2];
                #pragma unroll
                for (int np = 0; np < 4; np++) {
                    uint32_t r[4];
                    ldsm_x4(r, baseB + swz(b_row + np * 16, (k16 + b_col) * 2));
                    bf[np*2][0]   = r[0]; bf[np*2][1]   = r[1];
                    bf[np*2+1][0] = r[2]; bf[np*2+1][1] = r[3];
                }
                #pragma unroll
                for (int mt = 0; mt < 2; mt++)
                    #pragma unroll
                    for (int nt = 0; nt < 8; nt++)
                        mma_fp16(acc[mt][nt], af[mt], bf[nt]);
            }

            if (++s == NSTAGE) s = 0;
            if (++sn == NSTAGE) sn = 0;
        }
        asm volatile("cp.async.wait_group 0;" ::: "memory");

        // ---- epilogue for this segment ----
        const bool full = (k0 == 0) && (L == NKT1);
        const int ml0 = wm * 32 + (lane >> 2);
        const int nl0 = wn * 64 + (lane & 3) * 2;
        if (full) {
            #pragma unroll
            for (int mt = 0; mt < 2; mt++)
                #pragma unroll
                for (int half = 0; half < 2; half++) {
                    const int m = bm * BM + ml0 + mt * 16 + half * 8;
                    #pragma unroll
                    for (int nt = 0; nt < 8; nt++) {
                        const int n = bn * BN + nl0 + nt * 8;
                        float v0 = fmaxf(acc[mt][nt][half*2+0] + __ldg(&bias[n]),   0.f);
                        float v1 = fmaxf(acc[mt][nt][half*2+1] + __ldg(&bias[n+1]), 0.f);
                        *(uint32_t*)(Oh + (size_t)m * N1 + n) = pack2h(v0, v1);
                    }
                }
        } else {
            float* pp = ((k0 == 0) ? p0 : p1) + (size_t)t * (BM * BN);
            #pragma unroll
            for (int mt = 0; mt < 2; mt++)
                #pragma unroll
                for (int half = 0; half < 2; half++) {
                    const int ml = ml0 + mt * 16 + half * 8;
                    #pragma unroll
                    for (int nt = 0; nt < 8; nt++) {
                        const int nl = nl0 + nt * 8;
                        float2 fv;
                        fv.x = acc[mt][nt][half*2+0];
                        fv.y = acc[mt][nt][half*2+1];
                        *(float2*)(pp + ml * BN + nl) = fv;
                    }
                }
        }
        beg += L;
    }
}

// ---------------------------------------------------------------------------
// GEMM1 stream-K phase 2: combine partials for split tiles (deterministic).
// ---------------------------------------------------------------------------
__global__ __launch_bounds__(256) void gemm1_fix(
    const float* __restrict__ p0, const float* __restrict__ p1,
    const float* __restrict__ bias,
    __half* __restrict__ Oh)
{
    const int t = blockIdx.x;
    const unsigned long long lo = (unsigned long long)t * NKT1;
    unsigned long long c = ((lo + 1) * NCTA1 + U1 - 1) / U1;
    if (c < 1 || c > NCTA1 - 1) return;
    unsigned long long bnd = c * U1 / NCTA1;
    if (bnd >= lo + NKT1) return;   // no interior boundary -> tile was whole

    const int bm = t >> 3, bn = t & 7;
    const float* a = p0 + (size_t)t * (BM * BN);
    const float* b = p1 + (size_t)t * (BM * BN);

    #pragma unroll 4
    for (int j = 0; j < (BM * BN) / 256; j++) {
        const int idx = threadIdx.x + j * 256;
        const int ml = idx >> 7, nl = idx & 127;
        const int n = bn * BN + nl;
        float v = fmaxf(a[idx] + b[idx] + bias[n], 0.f);
        Oh[(size_t)(bm * BM + ml) * N1 + n] = __float2half_rn(v);
    }
}

// ---------------------------------------------------------------------------
// GEMM2 fused with final GEMV: y2 never materialized.
// Each warp reduces relu(acc+b2).w3 over its 64 columns; writes part[m][q],
// q = bn*2+wn in [0,8). Deterministic fixed-order reduction.
// ---------------------------------------------------------------------------
__global__ void __launch_bounds__(256, 2) gemm2_fused(
    const __half* __restrict__ A, const __half* __restrict__ B,
    const float* __restrict__ bias, const float* __restrict__ w3,
    float* __restrict__ part)
{
    extern __shared__ char smem[];
    const uint32_t sb  = smem_u32(smem);
    const int tid  = threadIdx.x;
    const int warp = tid >> 5, lane = tid & 31;
    const int wm   = warp & 3;
    const int wn   = warp >> 2;
    const int bn   = blockIdx.x, bm = blockIdx.y;
    const int nkt  = N1 / BK;   // K = N1 = 1024 -> 32 kt

    const char* pA = (const char*)(A + (size_t)bm * BM * N1);
    const char* pB = (const char*)(B + (size_t)bn * BN * N1);
    const size_t rowK = (size_t)N1 * 2;

    const int r0 = tid >> 2, c0 = tid & 3;
    const uint32_t s_off0 = swz(r0, c0 * 16);
    const uint32_t s_off1 = swz(r0 + 64, c0 * 16);
    const size_t  g_off0 = (size_t)r0 * rowK + c0 * 16;
    const size_t  g_off1 = (size_t)(r0 + 64) * rowK + c0 * 16;

    auto load_stage = [&](int s, int kt) {
        const uint32_t base = sb + s * STAGE_B;
        const size_t koff = (size_t)kt * (BK * 2);
        cp16(base + s_off0,          pA + g_off0 + koff);
        cp16(base + s_off1,          pA + g_off1 + koff);
        cp16(base + TILE_B + s_off0, pB + g_off0 + koff);
        cp16(base + TILE_B + s_off1, pB + g_off1 + koff);
    };

    float acc[2][8][4];
    #pragma unroll
    for (int i = 0; i < 2; i++)
        #pragma unroll
        for (int j = 0; j < 8; j++)
            #pragma unroll
            for (int r = 0; r < 4; r++) acc[i][j][r] = 0.f;

    #pragma unroll
    for (int pf = 0; pf < NSTAGE - 1; pf++) {
        if (pf < nkt) load_stage(pf, pf);
        asm volatile("cp.async.commit_group;" ::: "memory");
    }

    const int a_row = wm * 32 + (lane & 15);
    const int a_col = (lane >> 4) * 8;
    const int b_row = wn * 64 + ((lane >> 4) << 3) + (lane & 7);
    const int b_col = ((lane >> 3) & 1) * 8;

    int s = 0, sn = NSTAGE - 1;
    for (int kt = 0; kt < nkt; kt++) {
        asm volatile("cp.async.wait_group 4;" ::: "memory");
        __syncthreads();

        if (kt + NSTAGE - 1 < nkt) load_stage(sn, kt + NSTAGE - 1);
        asm volatile("cp.async.commit_group;" ::: "memory");

        const uint32_t baseA = sb + s * STAGE_B;
        const uint32_t baseB = baseA + TILE_B;

        #pragma unroll
        for (int ks = 0; ks < 2; ks++) {
            const int k16 = ks * 16;
            uint32_t af[2][4];
            #pragma unroll
            for (int mt = 0; mt < 2; mt++)
                ldsm_x4(af[mt], baseA + swz(a_row + mt * 16, (k16 + a_col) * 2));
            uint32_t bf[8][2];
            #pragma unroll
            for (int np = 0; np < 4; np++) {
                uint32_t r[4];
                ldsm_x4(r, baseB + swz(b_row + np * 16, (k16 + b_col) * 2));
                bf[np*2][0]   = r[0]; bf[np*2][1]   = r[1];
                bf[np*2+1][0] = r[2]; bf[np*2+1][1] = r[3];
            }
            #pragma unroll
            for (int mt = 0; mt < 2; mt++)
                #pragma unroll
                for (int nt = 0; nt < 8; nt++)
                    mma_fp16(acc[mt][nt], af[mt], bf[nt]);
        }

        if (++s == NSTAGE) s = 0;
        if (++sn == NSTAGE) sn = 0;
    }

    // ---- fused epilogue: relu + dot with w3, 4-lane reduce, write partial ----
    const int m_base = bm * BM + wm * 32 + (lane >> 2);
    const int n_base = bn * BN + wn * 64 + (lane & 3) * 2;
    const int q = bn * 2 + wn;   // 0..7
    #pragma unroll
    for (int mt = 0; mt < 2; mt++) {
        #pragma unroll
        for (int half = 0; half < 2; half++) {
            const int m = m_base + mt * 16 + half * 8;
            float s2 = 0.f;
            #pragma unroll
            for (int nt = 0; nt < 8; nt++) {
                const int n = n_base + nt * 8;
                float v0 = fmaxf(acc[mt][nt][half*2+0] + __ldg(&bias[n]),   0.f);
                float v1 = fmaxf(acc[mt][nt][half*2+1] + __ldg(&bias[n+1]), 0.f);
                s2 += v0 * __ldg(&w3[n]) + v1 * __ldg(&w3[n+1]);
            }
            s2 += __shfl_xor_sync(0xffffffffu, s2, 1);
            s2 += __shfl_xor_sync(0xffffffffu, s2, 2);
            if ((lane & 3) == 0) part[(size_t)m * 8 + q] = s2;
        }
    }
}

// ---------------------------------------------------------------------------
// Final: out[b] = sigmoid( sum_q part[b][q] + b3 )
// ---------------------------------------------------------------------------
__global__ __launch_bounds__(256) void final2_kernel(
    const float* __restrict__ part, const float* __restrict__ b3,
    float* __restrict__ out)
{
    const int row = blockIdx.x * 256 + threadIdx.x;
    float4 a = *(const float4*)(part + (size_t)row * 8);
    float4 b = *(const float4*)(part + (size_t)row * 8 + 4);
    float s = ((a.x + a.y) + (a.z + a.w)) + ((b.x + b.y) + (b.z + b.w)) + b3[0];
    out[row] = 1.f / (1.f + expf(-s));
}

// ---------------------------------------------------------------------------
extern "C" void kernel_launch(void* const* d_in, const int* in_sizes, int n_in,
                              void* d_out, int out_size)
{
    const float* emb   = (const float*)d_in[0];
    const float* bn_w  = (const float*)d_in[1];
    const float* bn_b  = (const float*)d_in[2];
    const float* bn_m  = (const float*)d_in[3];
    const float* bn_v  = (const float*)d_in[4];
    const float* se_w1 = (const float*)d_in[5];
    const float* se_w2 = (const float*)d_in[6];
    const float* w_bl  = (const float*)d_in[7];
    const float* d_w1  = (const float*)d_in[8];
    const float* d_b1  = (const float*)d_in[9];
    const float* d_w2  = (const float*)d_in[10];
    const float* d_b2  = (const float*)d_in[11];
    const float* d_w3  = (const float*)d_in[12];
    const float* d_b3  = (const float*)d_in[13];
    float* out = (float*)d_out;

    __half *h, *w1, *y1, *w2;
    float *part, *p0, *p1;
    cudaGetSymbolAddress((void**)&h,    g_h);
    cudaGetSymbolAddress((void**)&w1,   g_w1);
    cudaGetSymbolAddress((void**)&y1,   g_y1);
    cudaGetSymbolAddress((void**)&w2,   g_w2);
    cudaGetSymbolAddress((void**)&part, g_part);
    cudaGetSymbolAddress((void**)&p0,   g_p0);
    cudaGetSymbolAddress((void**)&p1,   g_p1);

    cudaFuncSetAttribute(gemm1_sk,    cudaFuncAttributeMaxDynamicSharedMemorySize, GEMM_SMEM);
    cudaFuncSetAttribute(gemm2_fused, cudaFuncAttributeMaxDynamicSharedMemorySize, GEMM_SMEM);

    // 1) feature construction (fp16)
    feat_kernel<<<B_SZ, 256>>>(emb, bn_w, bn_b, bn_m, bn_v, se_w1, se_w2, w_bl, h);

    // 2) weight converts (both in one launch)
    split_kernel<<<4096, 256>>>(d_w1, w1, d_w2, w2);

    // 3) GEMM1 stream-K: [8192,12480] x [1024,12480]^T + relu -> y1 (fp16)
    gemm1_sk<<<NCTA1, 256, GEMM_SMEM>>>(h, w1, d_b1, y1, p0, p1);
    gemm1_fix<<<NT1, 256>>>(p0, p1, d_b1, y1);

    // 4) GEMM2 + final GEMV fused -> part[8192][8]
    dim3 g2(N2 / BN, B_SZ / BM);
    gemm2_fused<<<g2, 256, GEMM_SMEM>>>(y1, w2, d_b2, d_w3, part);

    // 5) sum partials + sigmoid
    final2_kernel<<<B_SZ / 256, 256>>>(part, d_b3, out);
}

// round 17
// speedup vs baseline: 1.0809x; 1.0350x over previous
#include <cuda_runtime.h>
#include <cuda_fp16.h>
#include <stdint.h>
#include <math.h>

#define B_SZ 8192
#define F    40
#define E    8
#define FE   320
#define RDIM 5
#define P    780
#define K1   12480
#define N1   1024
#define N2   512

// ---- GEMM tiling ----
#define BM 128
#define BN 128
#define BK 32
#define TILE_B 8192                      // one matrix tile: 128 rows x 64B swizzled
#define STAGE_B (2 * TILE_B)             // A + B = 16KB
#define NSTAGE 6
#define GEMM_SMEM (NSTAGE * STAGE_B)     // 98304 -> 2 CTAs/SM

// ---- stream-K for GEMM1 ----
#define NKT1  (K1 / BK)                  // 390 kt per tile
#define NTM1  (B_SZ / BM)                // 64
#define NTN1  (N1 / BN)                  // 8
#define NT1   (NTM1 * NTN1)              // 512 tiles
#define NCTA1 296                        // 148 SMs x 2 CTAs
#define U1    ((size_t)NT1 * NKT1)       // 199680 work units

// -------------------- device scratch --------------------
__device__ __half g_h [(size_t)B_SZ * K1];
__device__ __half g_w1[(size_t)N1 * K1];
__device__ __half g_y1[(size_t)B_SZ * N1];
__device__ __half g_w2[(size_t)N2 * N1];
__device__ float  g_part[(size_t)B_SZ * 8];      // fused GEMM2+GEMV partials
__device__ __half g_p0[(size_t)NT1 * BM * BN];   // stream-K partial (k-head, fp16)
__device__ __half g_p1[(size_t)NT1 * BM * BN];   // stream-K partial (k-tail, fp16)

// -------------------- helpers --------------------
__device__ __forceinline__ uint32_t smem_u32(const void* p) {
    uint32_t a;
    asm("{ .reg .u64 t; cvta.to.shared.u64 t, %1; cvt.u32.u64 %0, t; }" : "=r"(a) : "l"(p));
    return a;
}
__device__ __forceinline__ void cp16(uint32_t dst, const void* src) {
    asm volatile("cp.async.cg.shared.global [%0], [%1], 16;" :: "r"(dst), "l"(src));
}
__device__ __forceinline__ void ldsm_x4(uint32_t* r, uint32_t addr) {
    asm volatile("ldmatrix.sync.aligned.m8n8.x4.shared.b16 {%0,%1,%2,%3}, [%4];"
                 : "=r"(r[0]), "=r"(r[1]), "=r"(r[2]), "=r"(r[3]) : "r"(addr));
}
__device__ __forceinline__ void mma_fp16(float* c, const uint32_t* a, const uint32_t* b) {
    asm volatile(
        "mma.sync.aligned.m16n8k16.row.col.f32.f16.f16.f32 "
        "{%0,%1,%2,%3}, {%4,%5,%6,%7}, {%8,%9}, {%0,%1,%2,%3};"
        : "+f"(c[0]), "+f"(c[1]), "+f"(c[2]), "+f"(c[3])
        : "r"(a[0]), "r"(a[1]), "r"(a[2]), "r"(a[3]), "r"(b[0]), "r"(b[1]));
}
// swizzled byte offset within an 8KB tile: row r (0..127), byte col bc (0..63, 16B-aligned)
__device__ __forceinline__ uint32_t swz(int r, int bc) {
    return (uint32_t)(r * 64 + ((((bc) >> 4) ^ ((r >> 1) & 3)) << 4));
}
__device__ __forceinline__ uint32_t pack2h(float a, float b) {
    __half2 h = __floats2half2_rn(a, b);
    return *(uint32_t*)&h;
}

// ---------------------------------------------------------------------------
// Fused: feat (blocks 0..8191) + weight convert (blocks 8192..12287).
// feat computes each pair product once; writes SE half and raw half together.
// ---------------------------------------------------------------------------
#define W1_Q ((size_t)N1 * K1 / 4)
#define W2_Q ((size_t)N2 * N1 / 4)
#define CVT_BLOCKS 4096

__global__ __launch_bounds__(256) void feat_cvt_kernel(
    const float* __restrict__ emb,  const float* __restrict__ bn_w,
    const float* __restrict__ bn_b, const float* __restrict__ bn_m,
    const float* __restrict__ bn_v, const float* __restrict__ se_w1,
    const float* __restrict__ se_w2,const float* __restrict__ w_bl,
    __half* __restrict__ h_out,
    const float* __restrict__ s1, __half* __restrict__ d1,
    const float* __restrict__ s2, __half* __restrict__ d2)
{
    const int tid = threadIdx.x;

    if (blockIdx.x >= B_SZ) {
        // ---- weight convert part ----
        const size_t total = W1_Q + W2_Q;
        for (size_t i = (size_t)(blockIdx.x - B_SZ) * 256 + tid; i < total;
             i += (size_t)CVT_BLOCKS * 256) {
            const float* src = (i < W1_Q) ? s1 : s2;
            __half*      dst = (i < W1_Q) ? d1 : d2;
            const size_t j   = (i < W1_Q) ? i : (i - W1_Q);
            float4 v = ((const float4*)src)[j];
            uint2 hv;
            hv.x = pack2h(v.x, v.y);
            hv.y = pack2h(v.z, v.w);
            *(uint2*)(dst + j * 4) = hv;
        }
        return;
    }

    // ---- feat part ----
    __shared__ float sV[FE], sT[FE], sZ[F], sH[RDIM], sA[F], sW[E*E];
    __shared__ unsigned char s_pi[P], s_pj[P];

    const int b = blockIdx.x;

    if (tid == 0) {
        int p = 0;
        for (int i = 0; i < F; i++)
            for (int j = i + 1; j < F; j++) { s_pi[p] = (unsigned char)i; s_pj[p] = (unsigned char)j; p++; }
    }
    if (tid < E*E) sW[tid] = w_bl[tid];

    for (int idx = tid; idx < FE; idx += 256) {
        float x   = emb[(size_t)b * FE + idx];
        float inv = rsqrtf(bn_v[idx] + 1e-5f);
        sV[idx]   = (x - bn_m[idx]) * inv * bn_w[idx] + bn_b[idx];
    }
    __syncthreads();

    if (tid < F) {
        float s = 0.f;
        #pragma unroll
        for (int e = 0; e < E; e++) s += sV[tid * E + e];
        sZ[tid] = s * (1.f / E);
    }
    __syncthreads();

    if (tid < RDIM) {
        float s = 0.f;
        #pragma unroll
        for (int f = 0; f < F; f++) s += sZ[f] * se_w1[tid * F + f];
        sH[tid] = fmaxf(s, 0.f);
    }
    __syncthreads();

    if (tid < F) {
        float s = 0.f;
        #pragma unroll
        for (int r = 0; r < RDIM; r++) s += sH[r] * se_w2[tid * RDIM + r];
        sA[tid] = fmaxf(s, 0.f);
    }

    for (int idx = tid; idx < FE; idx += 256) {
        int f = idx >> 3, d = idx & 7;
        float s = 0.f;
        #pragma unroll
        for (int e = 0; e < E; e++) s += sV[f * E + e] * sW[d * E + e];
        sT[idx] = s;
    }
    __syncthreads();

    __half* oh = h_out + (size_t)b * K1;
    for (int p = tid; p < P; p += 256) {
        const int i = s_pi[p], j = s_pj[p];
        const float sc = sA[i] * sA[j];
        const float4 ta = *(const float4*)&sT[i * E];
        const float4 tb = *(const float4*)&sT[i * E + 4];
        const float4 va = *(const float4*)&sV[j * E];
        const float4 vb = *(const float4*)&sV[j * E + 4];
        const float r0 = ta.x * va.x, r1 = ta.y * va.y;
        const float r2 = ta.z * va.z, r3 = ta.w * va.w;
        const float r4 = tb.x * vb.x, r5 = tb.y * vb.y;
        const float r6 = tb.z * vb.z, r7 = tb.w * vb.w;
        uint4 rv, svv;
        rv.x  = pack2h(r0, r1);            rv.y  = pack2h(r2, r3);
        rv.z  = pack2h(r4, r5);            rv.w  = pack2h(r6, r7);
        svv.x = pack2h(r0 * sc, r1 * sc);  svv.y = pack2h(r2 * sc, r3 * sc);
        svv.z = pack2h(r4 * sc, r5 * sc);  svv.w = pack2h(r6 * sc, r7 * sc);
        *(uint4*)(oh + (size_t)p * 8) = svv;                 // SE half
        *(uint4*)(oh + (size_t)(P + p) * 8) = rv;            // raw half
    }
}

// ---------------------------------------------------------------------------
// GEMM1 stream-K phase 1 (fp16): 296 persistent CTAs.
// 6-stage cp.async pipeline (lookahead 5 kt), single barrier per kt.
// Split-tile partials stored fp16.
// ---------------------------------------------------------------------------
__global__ void __launch_bounds__(256, 2) gemm1_sk(
    const __half* __restrict__ A, const __half* __restrict__ B,
    const float* __restrict__ bias,
    __half* __restrict__ Oh,
    __half* __restrict__ p0, __half* __restrict__ p1)
{
    extern __shared__ char smem[];
    const uint32_t sb  = smem_u32(smem);
    const int tid  = threadIdx.x;
    const int warp = tid >> 5, lane = tid & 31;
    const int wm   = warp & 3;
    const int wn   = warp >> 2;

    // per-thread load coords (2 x 16B chunks per matrix per kt)
    const int r0 = tid >> 2, c0 = tid & 3;
    const uint32_t s_off0 = swz(r0, c0 * 16);
    const uint32_t s_off1 = swz(r0 + 64, c0 * 16);
    const size_t rowK  = (size_t)K1 * 2;
    const size_t g_off0 = (size_t)r0 * rowK + c0 * 16;
    const size_t g_off1 = (size_t)(r0 + 64) * rowK + c0 * 16;

    // ldmatrix lane coords (tile-local)
    const int a_row = wm * 32 + (lane & 15);
    const int a_col = (lane >> 4) * 8;
    const int b_row = wn * 64 + ((lane >> 4) << 3) + (lane & 7);
    const int b_col = ((lane >> 3) & 1) * 8;

    size_t beg = (size_t)blockIdx.x       * U1 / NCTA1;
    size_t end = (size_t)(blockIdx.x + 1) * U1 / NCTA1;

    bool first_seg = true;
    while (beg < end) {
        const int t  = (int)(beg / NKT1);
        const int k0 = (int)(beg % NKT1);
        int L = NKT1 - k0;
        if ((size_t)L > end - beg) L = (int)(end - beg);
        const int bm = t >> 3, bn = t & 7;

        const char* pA = (const char*)(A + (size_t)bm * BM * K1);
        const char* pB = (const char*)(B + (size_t)bn * BN * K1);

        float acc[2][8][4];
        #pragma unroll
        for (int i = 0; i < 2; i++)
            #pragma unroll
            for (int j = 0; j < 8; j++)
                #pragma unroll
                for (int r = 0; r < 4; r++) acc[i][j][r] = 0.f;

        auto load_stage = [&](int s, int kt) {
            const uint32_t base = sb + s * STAGE_B;
            const size_t koff = (size_t)kt * (BK * 2);
            cp16(base + s_off0,          pA + g_off0 + koff);
            cp16(base + s_off1,          pA + g_off1 + koff);
            cp16(base + TILE_B + s_off0, pB + g_off0 + koff);
            cp16(base + TILE_B + s_off1, pB + g_off1 + koff);
        };

        // barrier between segments: last ldsm of prev segment vs new writes
        if (!first_seg) __syncthreads();
        first_seg = false;

        #pragma unroll
        for (int pf = 0; pf < NSTAGE - 1; pf++) {
            if (pf < L) load_stage(pf, k0 + pf);
            asm volatile("cp.async.commit_group;" ::: "memory");
        }

        int s = 0, sn = NSTAGE - 1;   // current stage, prefetch stage (ring)
        for (int i = 0; i < L; i++) {
            asm volatile("cp.async.wait_group 4;" ::: "memory");
            __syncthreads();

            if (i + NSTAGE - 1 < L) load_stage(sn, k0 + i + NSTAGE - 1);
            asm volatile("cp.async.commit_group;" ::: "memory");

            const uint32_t baseA = sb + s * STAGE_B;
            const uint32_t baseB = baseA + TILE_B;

            #pragma unroll
            for (int ks = 0; ks < 2; ks++) {
                const int k16 = ks * 16;
                uint32_t af[2][4];
                #pragma unroll
                for (int mt = 0; mt < 2; mt++)
                    ldsm_x4(af[mt], baseA + swz(a_row + mt * 16, (k16 + a_col) * 2));
                uint32_t bf[8][2];
                #pragma unroll
                for (int np = 0; np < 4; np++) {
                    uint32_t r[4];
                    ldsm_x4(r, baseB + swz(b_row + np * 16, (k16 + b_col) * 2));
                    bf[np*2][0]   = r[0]; bf[np*2][1]   = r[1];
                    bf[np*2+1][0] = r[2]; bf[np*2+1][1] = r[3];
                }
                #pragma unroll
                for (int mt = 0; mt < 2; mt++)
                    #pragma unroll
                    for (int nt = 0; nt < 8; nt++)
                        mma_fp16(acc[mt][nt], af[mt], bf[nt]);
            }

            if (++s == NSTAGE) s = 0;
            if (++sn == NSTAGE) sn = 0;
        }
        asm volatile("cp.async.wait_group 0;" ::: "memory");

        // ---- epilogue for this segment ----
        const bool full = (k0 == 0) && (L == NKT1);
        const int ml0 = wm * 32 + (lane >> 2);
        const int nl0 = wn * 64 + (lane & 3) * 2;
        if (full) {
            #pragma unroll
            for (int mt = 0; mt < 2; mt++)
                #pragma unroll
                for (int half = 0; half < 2; half++) {
                    const int m = bm * BM + ml0 + mt * 16 + half * 8;
                    #pragma unroll
                    for (int nt = 0; nt < 8; nt++) {
                        const int n = bn * BN + nl0 + nt * 8;
                        float v0 = fmaxf(acc[mt][nt][half*2+0] + __ldg(&bias[n]),   0.f);
                        float v1 = fmaxf(acc[mt][nt][half*2+1] + __ldg(&bias[n+1]), 0.f);
                        *(uint32_t*)(Oh + (size_t)m * N1 + n) = pack2h(v0, v1);
                    }
                }
        } else {
            __half* pp = ((k0 == 0) ? p0 : p1) + (size_t)t * (BM * BN);
            #pragma unroll
            for (int mt = 0; mt < 2; mt++)
                #pragma unroll
                for (int half = 0; half < 2; half++) {
                    const int ml = ml0 + mt * 16 + half * 8;
                    #pragma unroll
                    for (int nt = 0; nt < 8; nt++) {
                        const int nl = nl0 + nt * 8;
                        *(uint32_t*)(pp + ml * BN + nl) =
                            pack2h(acc[mt][nt][half*2+0], acc[mt][nt][half*2+1]);
                    }
                }
        }
        beg += L;
    }
}

// ---------------------------------------------------------------------------
// GEMM1 stream-K phase 2: combine fp16 partials for split tiles.
// ---------------------------------------------------------------------------
__global__ __launch_bounds__(256) void gemm1_fix(
    const __half* __restrict__ p0, const __half* __restrict__ p1,
    const float* __restrict__ bias,
    __half* __restrict__ Oh)
{
    const int t = blockIdx.x;
    const unsigned long long lo = (unsigned long long)t * NKT1;
    unsigned long long c = ((lo + 1) * NCTA1 + U1 - 1) / U1;
    if (c < 1 || c > NCTA1 - 1) return;
    unsigned long long bnd = c * U1 / NCTA1;
    if (bnd >= lo + NKT1) return;   // no interior boundary -> tile was whole

    const int bm = t >> 3, bn = t & 7;
    const __half2* a = (const __half2*)(p0 + (size_t)t * (BM * BN));
    const __half2* b = (const __half2*)(p1 + (size_t)t * (BM * BN));

    #pragma unroll 4
    for (int j = 0; j < (BM * BN) / 512; j++) {
        const int idx = threadIdx.x + j * 256;        // half2 index
        const int ml = idx >> 6, nl = (idx & 63) * 2;
        const int n = bn * BN + nl;
        float2 af = __half22float2(a[idx]);
        float2 bf = __half22float2(b[idx]);
        float v0 = fmaxf(af.x + bf.x + __ldg(&bias[n]),   0.f);
        float v1 = fmaxf(af.y + bf.y + __ldg(&bias[n+1]), 0.f);
        *(uint32_t*)(Oh + (size_t)(bm * BM + ml) * N1 + n) = pack2h(v0, v1);
    }
}

// ---------------------------------------------------------------------------
// GEMM2 fused with final GEMV: y2 never materialized.
// ---------------------------------------------------------------------------
__global__ void __launch_bounds__(256, 2) gemm2_fused(
    const __half* __restrict__ A, const __half* __restrict__ B,
    const float* __restrict__ bias, const float* __restrict__ w3,
    float* __restrict__ part)
{
    extern __shared__ char smem[];
    const uint32_t sb  = smem_u32(smem);
    const int tid  = threadIdx.x;
    const int warp = tid >> 5, lane = tid & 31;
    const int wm   = warp & 3;
    const int wn   = warp >> 2;
    const int bn   = blockIdx.x, bm = blockIdx.y;
    const int nkt  = N1 / BK;   // 32

    const char* pA = (const char*)(A + (size_t)bm * BM * N1);
    const char* pB = (const char*)(B + (size_t)bn * BN * N1);
    const size_t rowK = (size_t)N1 * 2;

    const int r0 = tid >> 2, c0 = tid & 3;
    const uint32_t s_off0 = swz(r0, c0 * 16);
    const uint32_t s_off1 = swz(r0 + 64, c0 * 16);
    const size_t  g_off0 = (size_t)r0 * rowK + c0 * 16;
    const size_t  g_off1 = (size_t)(r0 + 64) * rowK + c0 * 16;

    auto load_stage = [&](int s, int kt) {
        const uint32_t base = sb + s * STAGE_B;
        const size_t koff = (size_t)kt * (BK * 2);
        cp16(base + s_off0,          pA + g_off0 + koff);
        cp16(base + s_off1,          pA + g_off1 + koff);
        cp16(base + TILE_B + s_off0, pB + g_off0 + koff);
        cp16(base + TILE_B + s_off1, pB + g_off1 + koff);
    };

    float acc[2][8][4];
    #pragma unroll
    for (int i = 0; i < 2; i++)
        #pragma unroll
        for (int j = 0; j < 8; j++)
            #pragma unroll
            for (int r = 0; r < 4; r++) acc[i][j][r] = 0.f;

    #pragma unroll
    for (int pf = 0; pf < NSTAGE - 1; pf++) {
        if (pf < nkt) load_stage(pf, pf);
        asm volatile("cp.async.commit_group;" ::: "memory");
    }

    const int a_row = wm * 32 + (lane & 15);
    const int a_col = (lane >> 4) * 8;
    const int b_row = wn * 64 + ((lane >> 4) << 3) + (lane & 7);
    const int b_col = ((lane >> 3) & 1) * 8;

    int s = 0, sn = NSTAGE - 1;
    for (int kt = 0; kt < nkt; kt++) {
        asm volatile("cp.async.wait_group 4;" ::: "memory");
        __syncthreads();

        if (kt + NSTAGE - 1 < nkt) load_stage(sn, kt + NSTAGE - 1);
        asm volatile("cp.async.commit_group;" ::: "memory");

        const uint32_t baseA = sb + s * STAGE_B;
        const uint32_t baseB = baseA + TILE_B;

        #pragma unroll
        for (int ks = 0; ks < 2; ks++) {
            const int k16 = ks * 16;
            uint32_t af[2][4];
            #pragma unroll
            for (int mt = 0; mt < 2; mt++)
                ldsm_x4(af[mt], baseA + swz(a_row + mt * 16, (k16 + a_col) * 2));
            uint32_t bf[8][2];
            #pragma unroll
            for (int np = 0; np < 4; np++) {
                uint32_t r[4];
                ldsm_x4(r, baseB + swz(b_row + np * 16, (k16 + b_col) * 2));
                bf[np*2][0]   = r[0]; bf[np*2][1]   = r[1];
                bf[np*2+1][0] = r[2]; bf[np*2+1][1] = r[3];
            }
            #pragma unroll
            for (int mt = 0; mt < 2; mt++)
                #pragma unroll
                for (int nt = 0; nt < 8; nt++)
                    mma_fp16(acc[mt][nt], af[mt], bf[nt]);
        }

        if (++s == NSTAGE) s = 0;
        if (++sn == NSTAGE) sn = 0;
    }

    // ---- fused epilogue: relu + dot with w3, 4-lane reduce, write partial ----
    const int m_base = bm * BM + wm * 32 + (lane >> 2);
    const int n_base = bn * BN + wn * 64 + (lane & 3) * 2;
    const int q = bn * 2 + wn;   // 0..7
    #pragma unroll
    for (int mt = 0; mt < 2; mt++) {
        #pragma unroll
        for (int half = 0; half < 2; half++) {
            const int m = m_base + mt * 16 + half * 8;
            float s2 = 0.f;
            #pragma unroll
            for (int nt = 0; nt < 8; nt++) {
                const int n = n_base + nt * 8;
                float v0 = fmaxf(acc[mt][nt][half*2+0] + __ldg(&bias[n]),   0.f);
                float v1 = fmaxf(acc[mt][nt][half*2+1] + __ldg(&bias[n+1]), 0.f);
                s2 += v0 * __ldg(&w3[n]) + v1 * __ldg(&w3[n+1]);
            }
            s2 += __shfl_xor_sync(0xffffffffu, s2, 1);
            s2 += __shfl_xor_sync(0xffffffffu, s2, 2);
            if ((lane & 3) == 0) part[(size_t)m * 8 + q] = s2;
        }
    }
}

// ---------------------------------------------------------------------------
// Final: out[b] = sigmoid( sum_q part[b][q] + b3 )
// ---------------------------------------------------------------------------
__global__ __launch_bounds__(256) void final2_kernel(
    const float* __restrict__ part, const float* __restrict__ b3,
    float* __restrict__ out)
{
    const int row = blockIdx.x * 256 + threadIdx.x;
    float4 a = *(const float4*)(part + (size_t)row * 8);
    float4 b = *(const float4*)(part + (size_t)row * 8 + 4);
    float s = ((a.x + a.y) + (a.z + a.w)) + ((b.x + b.y) + (b.z + b.w)) + b3[0];
    out[row] = 1.f / (1.f + expf(-s));
}

// ---------------------------------------------------------------------------
extern "C" void kernel_launch(void* const* d_in, const int* in_sizes, int n_in,
                              void* d_out, int out_size)
{
    const float* emb   = (const float*)d_in[0];
    const float* bn_w  = (const float*)d_in[1];
    const float* bn_b  = (const float*)d_in[2];
    const float* bn_m  = (const float*)d_in[3];
    const float* bn_v  = (const float*)d_in[4];
    const float* se_w1 = (const float*)d_in[5];
    const float* se_w2 = (const float*)d_in[6];
    const float* w_bl  = (const float*)d_in[7];
    const float* d_w1  = (const float*)d_in[8];
    const float* d_b1  = (const float*)d_in[9];
    const float* d_w2  = (const float*)d_in[10];
    const float* d_b2  = (const float*)d_in[11];
    const float* d_w3  = (const float*)d_in[12];
    const float* d_b3  = (const float*)d_in[13];
    float* out = (float*)d_out;

    __half *h, *w1, *y1, *w2, *p0, *p1;
    float *part;
    cudaGetSymbolAddress((void**)&h,    g_h);
    cudaGetSymbolAddress((void**)&w1,   g_w1);
    cudaGetSymbolAddress((void**)&y1,   g_y1);
    cudaGetSymbolAddress((void**)&w2,   g_w2);
    cudaGetSymbolAddress((void**)&part, g_part);
    cudaGetSymbolAddress((void**)&p0,   g_p0);
    cudaGetSymbolAddress((void**)&p1,   g_p1);

    cudaFuncSetAttribute(gemm1_sk,    cudaFuncAttributeMaxDynamicSharedMemorySize, GEMM_SMEM);
    cudaFuncSetAttribute(gemm2_fused, cudaFuncAttributeMaxDynamicSharedMemorySize, GEMM_SMEM);

    // 1) feature construction + weight converts (one launch)
    feat_cvt_kernel<<<B_SZ + CVT_BLOCKS, 256>>>(
        emb, bn_w, bn_b, bn_m, bn_v, se_w1, se_w2, w_bl, h,
        d_w1, w1, d_w2, w2);

    // 2) GEMM1 stream-K: [8192,12480] x [1024,12480]^T + relu -> y1 (fp16)
    gemm1_sk<<<NCTA1, 256, GEMM_SMEM>>>(h, w1, d_b1, y1, p0, p1);
    gemm1_fix<<<NT1, 256>>>(p0, p1, d_b1, y1);

    // 3) GEMM2 + final GEMV fused -> part[8192][8]
    dim3 g2(N2 / BN, B_SZ / BM);
    gemm2_fused<<<g2, 256, GEMM_SMEM>>>(y1, w2, d_b2, d_w3, part);

    // 4) sum partials + sigmoid
    final2_kernel<<<B_SZ / 256, 256>>>(part, d_b3, out);
}